// round 9
// baseline (speedup 1.0000x reference)
#include <cuda_runtime.h>
#include <math.h>

#define T_NUMC   1024
#define DET_NUMC 1024
#define EE       65536       // T_NUM * DEG
#define TWO_E    131072
#define NNODES   2048
#define D_EMBC   256
#define LAMC     5.0f
#define EPSC     1e-9f

// ---------------- scratch (device globals; no allocation allowed) ----------------
__device__ float g_node[NNODES * D_EMBC];
__device__ float g_P[NNODES * 64];
__device__ float g_Q[NNODES * 64];
__device__ float g_emb[TWO_E];
__device__ float g_msg[NNODES * D_EMBC];
__device__ float g_outf[NNODES * D_EMBC];
__device__ float g_norm[NNODES];
__device__ int   g_cnt[NNODES];
__device__ int   g_csc_eid[NNODES * 64];
__device__ int   g_csc_src[NNODES * 64];
__device__ float g_mval[EE];    // M0 nnz, row-major by tracklet (edge e -> row e/64)
__device__ int   g_dstd[EE];    // det column of edge e
__device__ float g_cval[EE];    // M0 nnz, column-major by det
__device__ int   g_csrc[EE];    // tracklet row of column-ordered nnz
__device__ float g_u[1025];
__device__ float g_v[1025];

__device__ __forceinline__ float warpsum(float x) {
    #pragma unroll
    for (int o = 16; o > 0; o >>= 1) x += __shfl_xor_sync(0xffffffffu, x, o);
    return x;
}

// ---------------- init: zero CSC counters, u=v=1 ----------------------------------
__global__ void init_kernel() {
    int i = blockIdx.x * blockDim.x + threadIdx.x;
    if (i < NNODES) g_cnt[i] = 0;
    if (i < 1025) { g_u[i] = 1.f; g_v[i] = 1.f; }
}

// ---------------- CSC build over all 2E edges (dst -> list of (edge, src)) ------
__global__ void csc_build(const int* __restrict__ ei) {
    int e = blockIdx.x * blockDim.x + threadIdx.x;
    if (e >= TWO_E) return;
    int d = ei[TWO_E + e];
    int slot = atomicAdd(&g_cnt[d], 1);
    if (slot < 64) {
        g_csc_eid[d * 64 + slot] = e;
        g_csc_src[d * 64 + slot] = ei[e];
    }
}

// ---------------- tiled fp32 GEMM: C = [relu]( A@B (+ A2@B2) (+ bias) ) ---------
template <bool RELU, bool DUAL>
__global__ void sgemm(const float* __restrict__ A, const float* __restrict__ B,
                      const float* __restrict__ A2, const float* __restrict__ B2,
                      const float* __restrict__ bias, float* __restrict__ C,
                      int M, int N, int K) {
    __shared__ float As[64][16];
    __shared__ float Bs[16][64];
    __shared__ float As2[DUAL ? 64 : 1][16];
    __shared__ float Bs2[DUAL ? 16 : 1][64];

    int tid = threadIdx.x;
    int rowB = blockIdx.y * 64, colB = blockIdx.x * 64;
    int tx = tid & 15, ty = tid >> 4;
    int ar = tid >> 2, ac = (tid & 3) << 2;
    int br = tid >> 4, bc = (tid & 15) << 2;

    float acc[4][4] = {};

    for (int k0 = 0; k0 < K; k0 += 16) {
        *(float4*)&As[ar][ac] = *(const float4*)&A[(size_t)(rowB + ar) * K + k0 + ac];
        *(float4*)&Bs[br][bc] = *(const float4*)&B[(size_t)(k0 + br) * N + colB + bc];
        if (DUAL) {
            *(float4*)&As2[ar][ac] = *(const float4*)&A2[(size_t)(rowB + ar) * K + k0 + ac];
            *(float4*)&Bs2[br][bc] = *(const float4*)&B2[(size_t)(k0 + br) * N + colB + bc];
        }
        __syncthreads();
        #pragma unroll
        for (int kk = 0; kk < 16; kk++) {
            float a[4];
            #pragma unroll
            for (int i = 0; i < 4; i++) a[i] = As[ty * 4 + i][kk];
            float4 bv = *(float4*)&Bs[kk][tx * 4];
            #pragma unroll
            for (int i = 0; i < 4; i++) {
                acc[i][0] += a[i] * bv.x;
                acc[i][1] += a[i] * bv.y;
                acc[i][2] += a[i] * bv.z;
                acc[i][3] += a[i] * bv.w;
            }
            if (DUAL) {
                float a2[4];
                #pragma unroll
                for (int i = 0; i < 4; i++) a2[i] = As2[ty * 4 + i][kk];
                float4 bv2 = *(float4*)&Bs2[kk][tx * 4];
                #pragma unroll
                for (int i = 0; i < 4; i++) {
                    acc[i][0] += a2[i] * bv2.x;
                    acc[i][1] += a2[i] * bv2.y;
                    acc[i][2] += a2[i] * bv2.z;
                    acc[i][3] += a2[i] * bv2.w;
                }
            }
        }
        __syncthreads();
    }
    #pragma unroll
    for (int i = 0; i < 4; i++) {
        int row = rowB + ty * 4 + i;
        #pragma unroll
        for (int j = 0; j < 4; j++) {
            int col = colB + tx * 4 + j;
            float v = acc[i][j];
            if (bias) v += bias[col];
            if (RELU) v = fmaxf(v, 0.f);
            C[(size_t)row * N + col] = v;
        }
    }
}

// ---------------- per-edge MLPs using P/Q factorization (thread per edge) --------
__global__ void edge_pq(const int* __restrict__ ei, const float* __restrict__ coords,
                        const float* __restrict__ W2a, const float* __restrict__ b2a,
                        const float* __restrict__ W1g, const float* __restrict__ b1g,
                        const float* __restrict__ W2g, const float* __restrict__ b2g,
                        const float* __restrict__ W1f, const float* __restrict__ b1f,
                        const float* __restrict__ W2f, const float* __restrict__ b2f) {
    int e = blockIdx.x * blockDim.x + threadIdx.x;
    if (e >= TWO_E) return;
    int s = ei[e], d = ei[TWO_E + e];

    const float4* Ps = (const float4*)(g_P + (size_t)s * 64);
    const float4* Qd = (const float4*)(g_Q + (size_t)d * 64);
    const float4* W2a4 = (const float4*)W2a;
    float a1 = b2a[0];
    #pragma unroll 4
    for (int h4 = 0; h4 < 16; h4++) {
        float4 pv = Ps[h4], qv = Qd[h4], wv = W2a4[h4];
        a1 += fmaxf(pv.x + qv.x, 0.f) * wv.x;
        a1 += fmaxf(pv.y + qv.y, 0.f) * wv.y;
        a1 += fmaxf(pv.z + qv.z, 0.f) * wv.z;
        a1 += fmaxf(pv.w + qv.w, 0.f) * wv.w;
    }

    float geo[8];
    float4 cs = *(const float4*)(coords + s * 4);
    float4 cd = *(const float4*)(coords + d * 4);
    geo[0] = cs.x; geo[1] = cs.y; geo[2] = cs.z; geo[3] = cs.w;
    geo[4] = cd.x; geo[5] = cd.y; geo[6] = cd.z; geo[7] = cd.w;
    float a2 = b2g[0];
    #pragma unroll
    for (int h = 0; h < 16; h++) {
        float acc = b1g[h];
        #pragma unroll
        for (int j = 0; j < 8; j++) acc += geo[j] * W1g[j * 16 + h];
        a2 += fmaxf(acc, 0.f) * W2g[h];
    }

    float ev = b2f[0];
    #pragma unroll
    for (int h = 0; h < 8; h++)
        ev += fmaxf(a1 * W1f[h] + a2 * W1f[8 + h] + b1f[h], 0.f) * W2f[h];
    g_emb[e] = ev;
}

// ---------------- msg: thread per (node, feature) --------------------------------
__global__ void msg_lit() {
    int idx = blockIdx.x * blockDim.x + threadIdx.x;  // 2048*256
    if (idx >= NNODES * D_EMBC) return;
    int n = idx / D_EMBC, f = idx % D_EMBC;
    float acc = 0.f;
    for (int k = 0; k < 64; k++) {
        int e  = g_csc_eid[n * 64 + k];
        int sn = g_csc_src[n * 64 + k];
        acc += g_emb[e] * g_node[(size_t)sn * D_EMBC + f];
    }
    g_msg[idx] = acc;
}

// ---------------- per-node L2 norm (thread per node) ------------------------------
__global__ void norm_lit() {
    int n = blockIdx.x * blockDim.x + threadIdx.x;
    if (n >= NNODES) return;
    const float4* r = (const float4*)(g_outf + (size_t)n * D_EMBC);
    float s = 0.f;
    for (int i = 0; i < D_EMBC / 4; i++) {
        float4 v = r[i];
        s += v.x * v.x + v.y * v.y + v.z * v.z + v.w * v.w;
    }
    g_norm[n] = sqrtf(s);
}

// ---------------- affinity -> M0 nnz values (thread per forward edge) ------------
__global__ void aff_lit(const int* __restrict__ ei, const float* __restrict__ co,
                        const float* __restrict__ W1c, const float* __restrict__ b1c,
                        const float* __restrict__ W2c, const float* __restrict__ b2c) {
    int e = blockIdx.x * blockDim.x + threadIdx.x;
    if (e >= EE) return;
    int t = ei[e], dn = ei[TWO_E + e];
    const float4* oa = (const float4*)(g_outf + (size_t)t  * D_EMBC);
    const float4* ob = (const float4*)(g_outf + (size_t)dn * D_EMBC);
    float dot = 0.f;
    for (int i = 0; i < D_EMBC / 4; i++) {
        float4 a = oa[i], b = ob[i];
        dot += a.x * b.x + a.y * b.y + a.z * b.z + a.w * b.w;
    }
    float cosv = dot / fmaxf(g_norm[t] * g_norm[dn], 1e-6f);

    float4 A = *(const float4*)(co + t * 4);
    float4 B = *(const float4*)(co + dn * 4);
    float lt0 = fmaxf(A.x, B.x), lt1 = fmaxf(A.y, B.y);
    float rb0 = fminf(A.z, B.z), rb1 = fminf(A.w, B.w);
    float w = fmaxf(rb0 - lt0, 0.f), h = fmaxf(rb1 - lt1, 0.f);
    float inter = w * h;
    float areaA = (A.z - A.x) * (A.w - A.y);
    float areaB = (B.z - B.x) * (B.w - B.y);
    float iou = inter / (areaA + areaB - inter + 1e-9f);

    float aff = b2c[0];
    #pragma unroll
    for (int hh = 0; hh < 8; hh++)
        aff += fmaxf(cosv * W1c[hh] + iou * W1c[8 + hh] + b1c[hh], 0.f) * W2c[hh];
    g_mval[e] = expf(aff * LAMC);
    g_dstd[e] = dn - T_NUMC;
}

// ---------------- pack column view of M0 nnz (det-major) -------------------------
__global__ void csc_pack() {
    int idx = blockIdx.x * blockDim.x + threadIdx.x;  // EE threads
    int c = idx >> 6, k = idx & 63;
    int base = (T_NUMC + c) * 64 + k;                 // CSC of det node T+c: fwd edges only
    g_cval[idx] = g_mval[g_csc_eid[base]];
    g_csrc[idx] = g_csc_src[base];
}

// ---------------- factorized sinkhorn half-steps: M = diag(u) M0 diag(v) ---------
// row:  s_r = sum_nnz mval*v[col] + slack*v[1024];  u_r' = u_r/(u_r*s_r + eps)
__global__ void sink_row(float slack) {
    int b = blockIdx.x, tid = threadIdx.x;
    if (b < 4) {
        int r = b * 256 + tid;
        float s = slack * g_v[1024];
        const float* mv = g_mval + r * 64;
        const int*   dp = g_dstd + r * 64;
        #pragma unroll 8
        for (int k = 0; k < 64; k++) s += mv[k] * g_v[dp[k]];
        float ur = g_u[r];
        g_u[r] = ur / (ur * s + EPSC);
    } else {
        // slack row 1024: s = slack * sum_j v_j
        float s = 0.f;
        for (int i = tid; i < 1025; i += 256) s += g_v[i];
        __shared__ float red[8];
        float w = warpsum(s);
        if ((tid & 31) == 0) red[tid >> 5] = w;
        __syncthreads();
        if (tid == 0) {
            float tot = 0.f;
            #pragma unroll
            for (int i = 0; i < 8; i++) tot += red[i];
            float ur = g_u[1024];
            g_u[1024] = ur / (ur * slack * tot + EPSC);
        }
    }
}

__global__ void sink_col(float slack) {
    int b = blockIdx.x, tid = threadIdx.x;
    if (b < 4) {
        int c = b * 256 + tid;
        float s = slack * g_u[1024];
        const float* cv = g_cval + c * 64;
        const int*   sp = g_csrc + c * 64;
        #pragma unroll 8
        for (int k = 0; k < 64; k++) s += cv[k] * g_u[sp[k]];
        float vc = g_v[c];
        g_v[c] = vc / (vc * s + EPSC);
    } else {
        float s = 0.f;
        for (int i = tid; i < 1025; i += 256) s += g_u[i];
        __shared__ float red[8];
        float w = warpsum(s);
        if ((tid & 31) == 0) red[tid >> 5] = w;
        __syncthreads();
        if (tid == 0) {
            float tot = 0.f;
            #pragma unroll
            for (int i = 0; i < 8; i++) tot += red[i];
            float vc = g_v[1024];
            g_v[1024] = vc / (vc * slack * tot + EPSC);
        }
    }
}

// ---------------- final scatter: out[t,d] = u[t]*M0*v[d]; scalars ----------------
__global__ void out_scatter(float* __restrict__ out, int out_size) {
    int e = blockIdx.x * blockDim.x + threadIdx.x;
    if (e < EE) {
        int t = e >> 6;                 // forward edge e belongs to tracklet e/64
        int d = g_dstd[e];
        out[(size_t)t * DET_NUMC + d] = g_u[t] * g_mval[e] * g_v[d];
    }
    if (e == 0 && out_size >= 2097154) {
        out[2097152] = 1024.0f;  // det_num
        out[2097153] = 1024.0f;  // tracklet_num
    }
}

// =================================================================================
extern "C" void kernel_launch(void* const* d_in, const int* in_sizes, int n_in,
                              void* d_out, int out_size) {
    const float* x      = (const float*)d_in[0];
    const float* coords = (const float*)d_in[1];   // U[0,1) coords -> geo MLP
    const float* co     = (const float*)d_in[2];   // coords_original -> IoU
    const float* gt     = (const float*)d_in[3];
    const int*   ei     = (const int*)  d_in[4];
    const float* W_enc  = (const float*)d_in[5];
    const float* b_enc  = (const float*)d_in[6];
    const float* W1a    = (const float*)d_in[7];
    const float* b1a    = (const float*)d_in[8];
    const float* W2a    = (const float*)d_in[9];
    const float* b2a    = (const float*)d_in[10];
    const float* W1g    = (const float*)d_in[11];
    const float* b1g    = (const float*)d_in[12];
    const float* W2g    = (const float*)d_in[13];
    const float* b2g    = (const float*)d_in[14];
    const float* W1f    = (const float*)d_in[15];
    const float* b1f    = (const float*)d_in[16];
    const float* W2f    = (const float*)d_in[17];
    const float* b2f    = (const float*)d_in[18];
    const float* Wn     = (const float*)d_in[19];
    const float* Wm     = (const float*)d_in[20];
    const float* bo     = (const float*)d_in[21];
    const float* W1c    = (const float*)d_in[22];
    const float* b1c    = (const float*)d_in[23];
    const float* W2c    = (const float*)d_in[24];
    const float* b2c    = (const float*)d_in[25];

    void* p;
    cudaGetSymbolAddress(&p, g_node); float* node = (float*)p;
    cudaGetSymbolAddress(&p, g_P);    float* Pp   = (float*)p;
    cudaGetSymbolAddress(&p, g_Q);    float* Qp   = (float*)p;
    cudaGetSymbolAddress(&p, g_msg);  float* msgp = (float*)p;
    cudaGetSymbolAddress(&p, g_outf); float* outp = (float*)p;

    init_kernel<<<8, 512>>>();
    csc_build<<<TWO_E / 256, 256>>>(ei);

    // node = relu(x @ W_enc + b_enc)
    sgemm<true,  false><<<dim3(4, 32), 256>>>(x, W_enc, nullptr, nullptr, b_enc,
                                              node, NNODES, D_EMBC, 512);
    // P = node @ W1a[:256] + b1a ;  Q = node @ W1a[256:]
    sgemm<false, false><<<dim3(1, 32), 256>>>(node, W1a, nullptr, nullptr, b1a,
                                              Pp, NNODES, 64, D_EMBC);
    sgemm<false, false><<<dim3(1, 32), 256>>>(node, W1a + 256 * 64, nullptr, nullptr, nullptr,
                                              Qp, NNODES, 64, D_EMBC);

    edge_pq<<<TWO_E / 256, 256>>>(ei, coords, W2a, b2a,
                                  W1g, b1g, W2g, b2g, W1f, b1f, W2f, b2f);
    msg_lit<<<(NNODES * D_EMBC) / 256, 256>>>();

    // out = relu(node @ Wn + msg @ Wm + bo)
    sgemm<true, true><<<dim3(4, 32), 256>>>(node, Wn, msgp, Wm, bo,
                                            outp, NNODES, D_EMBC, D_EMBC);

    norm_lit<<<NNODES / 256, 256>>>();
    aff_lit<<<EE / 256, 256>>>(ei, co, W1c, b1c, W2c, b2c);
    csc_pack<<<EE / 256, 256>>>();

    float slack = expf(-1.0f);  // exp(SLACK*LAM)
    for (int it = 0; it < 8; it++) {
        sink_row<<<5, 256>>>(slack);
        sink_col<<<5, 256>>>(slack);
    }

    cudaMemsetAsync(d_out, 0, (size_t)T_NUMC * DET_NUMC * sizeof(float), 0);
    out_scatter<<<EE / 256, 256>>>((float*)d_out, out_size);
    if (out_size >= 2097152)
        cudaMemcpyAsync((float*)d_out + 1048576, gt, 1048576 * sizeof(float),
                        cudaMemcpyDeviceToDevice, 0);
}

// round 10
// speedup vs baseline: 2.4545x; 2.4545x over previous
#include <cuda_runtime.h>
#include <math.h>

#define T_NUMC   1024
#define DET_NUMC 1024
#define EE       65536       // T_NUM * DEG
#define TWO_E    131072
#define NNODES   2048
#define D_EMBC   256
#define LAMC     5.0f
#define EPSC     1e-9f

// ---------------- scratch (device globals; no allocation allowed) ----------------
__device__ float g_node[NNODES * D_EMBC];
__device__ float g_P[NNODES * 64];
__device__ float g_Q[NNODES * 64];
__device__ float g_emb[TWO_E];
__device__ float g_msg[NNODES * D_EMBC];
__device__ float g_outf[NNODES * D_EMBC];
__device__ float g_norm[NNODES];
__device__ int   g_cnt[NNODES];
__device__ int   g_csc_eid[NNODES * 64];
__device__ int   g_csc_src[NNODES * 64];
__device__ float g_mval[EE];    // M0 nnz, row-major by tracklet (edge e -> row e/64)
__device__ int   g_dstd[EE];    // det column of edge e
__device__ float g_cval[EE];    // M0 nnz, column-major by det
__device__ int   g_csrc[EE];    // tracklet row of column-ordered nnz
__device__ float g_u[1025];
__device__ float g_v[1025];

__device__ __forceinline__ float warpsum(float x) {
    #pragma unroll
    for (int o = 16; o > 0; o >>= 1) x += __shfl_xor_sync(0xffffffffu, x, o);
    return x;
}

// ---------------- init: zero CSC counters, u=v=1 ----------------------------------
__global__ void init_kernel() {
    int i = blockIdx.x * blockDim.x + threadIdx.x;
    if (i < NNODES) g_cnt[i] = 0;
    if (i < 1025) { g_u[i] = 1.f; g_v[i] = 1.f; }
}

// ---------------- CSC build over all 2E edges (dst -> list of (edge, src)) ------
__global__ void csc_build(const int* __restrict__ ei) {
    int e = blockIdx.x * blockDim.x + threadIdx.x;
    if (e >= TWO_E) return;
    int d = ei[TWO_E + e];
    int slot = atomicAdd(&g_cnt[d], 1);
    if (slot < 64) {
        g_csc_eid[d * 64 + slot] = e;
        g_csc_src[d * 64 + slot] = ei[e];
    }
}

// ---------------- tiled fp32 GEMM: C = [relu]( A@B (+ A2@B2) (+ bias) ) ---------
template <bool RELU, bool DUAL>
__global__ void sgemm(const float* __restrict__ A, const float* __restrict__ B,
                      const float* __restrict__ A2, const float* __restrict__ B2,
                      const float* __restrict__ bias, float* __restrict__ C,
                      int M, int N, int K) {
    __shared__ float As[64][16];
    __shared__ float Bs[16][64];
    __shared__ float As2[DUAL ? 64 : 1][16];
    __shared__ float Bs2[DUAL ? 16 : 1][64];

    int tid = threadIdx.x;
    int rowB = blockIdx.y * 64, colB = blockIdx.x * 64;
    int tx = tid & 15, ty = tid >> 4;
    int ar = tid >> 2, ac = (tid & 3) << 2;
    int br = tid >> 4, bc = (tid & 15) << 2;

    float acc[4][4] = {};

    for (int k0 = 0; k0 < K; k0 += 16) {
        *(float4*)&As[ar][ac] = *(const float4*)&A[(size_t)(rowB + ar) * K + k0 + ac];
        *(float4*)&Bs[br][bc] = *(const float4*)&B[(size_t)(k0 + br) * N + colB + bc];
        if (DUAL) {
            *(float4*)&As2[ar][ac] = *(const float4*)&A2[(size_t)(rowB + ar) * K + k0 + ac];
            *(float4*)&Bs2[br][bc] = *(const float4*)&B2[(size_t)(k0 + br) * N + colB + bc];
        }
        __syncthreads();
        #pragma unroll
        for (int kk = 0; kk < 16; kk++) {
            float a[4];
            #pragma unroll
            for (int i = 0; i < 4; i++) a[i] = As[ty * 4 + i][kk];
            float4 bv = *(float4*)&Bs[kk][tx * 4];
            #pragma unroll
            for (int i = 0; i < 4; i++) {
                acc[i][0] += a[i] * bv.x;
                acc[i][1] += a[i] * bv.y;
                acc[i][2] += a[i] * bv.z;
                acc[i][3] += a[i] * bv.w;
            }
            if (DUAL) {
                float a2[4];
                #pragma unroll
                for (int i = 0; i < 4; i++) a2[i] = As2[ty * 4 + i][kk];
                float4 bv2 = *(float4*)&Bs2[kk][tx * 4];
                #pragma unroll
                for (int i = 0; i < 4; i++) {
                    acc[i][0] += a2[i] * bv2.x;
                    acc[i][1] += a2[i] * bv2.y;
                    acc[i][2] += a2[i] * bv2.z;
                    acc[i][3] += a2[i] * bv2.w;
                }
            }
        }
        __syncthreads();
    }
    #pragma unroll
    for (int i = 0; i < 4; i++) {
        int row = rowB + ty * 4 + i;
        #pragma unroll
        for (int j = 0; j < 4; j++) {
            int col = colB + tx * 4 + j;
            float v = acc[i][j];
            if (bias) v += bias[col];
            if (RELU) v = fmaxf(v, 0.f);
            C[(size_t)row * N + col] = v;
        }
    }
}

// ---------------- fused P/Q GEMM: one launch, blockIdx.x selects P or Q ----------
// P = node @ W1a[0:256] + b1a ; Q = node @ W1a[256:512].  N=64, K=256, BM=64.
__global__ void pq_gemm(const float* __restrict__ A, const float* __restrict__ W1a,
                        const float* __restrict__ b1a) {
    __shared__ float As[64][16];
    __shared__ float Bs[16][64];

    int tid = threadIdx.x;
    int rowB = blockIdx.y * 64;
    bool isQ = (blockIdx.x == 1);
    const float* B = W1a + (isQ ? 256 * 64 : 0);
    float* C = isQ ? g_Q : g_P;

    int tx = tid & 15, ty = tid >> 4;
    int ar = tid >> 2, ac = (tid & 3) << 2;
    int br = tid >> 4, bc = (tid & 15) << 2;

    float acc[4][4] = {};

    for (int k0 = 0; k0 < 256; k0 += 16) {
        *(float4*)&As[ar][ac] = *(const float4*)&A[(size_t)(rowB + ar) * 256 + k0 + ac];
        *(float4*)&Bs[br][bc] = *(const float4*)&B[(size_t)(k0 + br) * 64 + bc];
        __syncthreads();
        #pragma unroll
        for (int kk = 0; kk < 16; kk++) {
            float a[4];
            #pragma unroll
            for (int i = 0; i < 4; i++) a[i] = As[ty * 4 + i][kk];
            float4 bv = *(float4*)&Bs[kk][tx * 4];
            #pragma unroll
            for (int i = 0; i < 4; i++) {
                acc[i][0] += a[i] * bv.x;
                acc[i][1] += a[i] * bv.y;
                acc[i][2] += a[i] * bv.z;
                acc[i][3] += a[i] * bv.w;
            }
        }
        __syncthreads();
    }
    #pragma unroll
    for (int i = 0; i < 4; i++) {
        int row = rowB + ty * 4 + i;
        #pragma unroll
        for (int j = 0; j < 4; j++) {
            int col = tx * 4 + j;
            float v = acc[i][j];
            if (!isQ) v += b1a[col];
            C[(size_t)row * 64 + col] = v;
        }
    }
}

// ---------------- per-edge MLPs using P/Q factorization (thread per edge) --------
__global__ void edge_pq(const int* __restrict__ ei, const float* __restrict__ coords,
                        const float* __restrict__ W2a, const float* __restrict__ b2a,
                        const float* __restrict__ W1g, const float* __restrict__ b1g,
                        const float* __restrict__ W2g, const float* __restrict__ b2g,
                        const float* __restrict__ W1f, const float* __restrict__ b1f,
                        const float* __restrict__ W2f, const float* __restrict__ b2f) {
    int e = blockIdx.x * blockDim.x + threadIdx.x;
    if (e >= TWO_E) return;
    int s = ei[e], d = ei[TWO_E + e];

    const float4* Ps = (const float4*)(g_P + (size_t)s * 64);
    const float4* Qd = (const float4*)(g_Q + (size_t)d * 64);
    const float4* W2a4 = (const float4*)W2a;
    float a1 = b2a[0];
    #pragma unroll 4
    for (int h4 = 0; h4 < 16; h4++) {
        float4 pv = Ps[h4], qv = Qd[h4], wv = W2a4[h4];
        a1 += fmaxf(pv.x + qv.x, 0.f) * wv.x;
        a1 += fmaxf(pv.y + qv.y, 0.f) * wv.y;
        a1 += fmaxf(pv.z + qv.z, 0.f) * wv.z;
        a1 += fmaxf(pv.w + qv.w, 0.f) * wv.w;
    }

    float geo[8];
    float4 cs = *(const float4*)(coords + s * 4);
    float4 cd = *(const float4*)(coords + d * 4);
    geo[0] = cs.x; geo[1] = cs.y; geo[2] = cs.z; geo[3] = cs.w;
    geo[4] = cd.x; geo[5] = cd.y; geo[6] = cd.z; geo[7] = cd.w;
    float a2 = b2g[0];
    #pragma unroll
    for (int h = 0; h < 16; h++) {
        float acc = b1g[h];
        #pragma unroll
        for (int j = 0; j < 8; j++) acc += geo[j] * W1g[j * 16 + h];
        a2 += fmaxf(acc, 0.f) * W2g[h];
    }

    float ev = b2f[0];
    #pragma unroll
    for (int h = 0; h < 8; h++)
        ev += fmaxf(a1 * W1f[h] + a2 * W1f[8 + h] + b1f[h], 0.f) * W2f[h];
    g_emb[e] = ev;
}

// ---------------- msg: thread per (node, feature) --------------------------------
__global__ void msg_lit() {
    int idx = blockIdx.x * blockDim.x + threadIdx.x;  // 2048*256
    if (idx >= NNODES * D_EMBC) return;
    int n = idx / D_EMBC, f = idx % D_EMBC;
    float acc = 0.f;
    for (int k = 0; k < 64; k++) {
        int e  = g_csc_eid[n * 64 + k];
        int sn = g_csc_src[n * 64 + k];
        acc += g_emb[e] * g_node[(size_t)sn * D_EMBC + f];
    }
    g_msg[idx] = acc;
}

// ---------------- per-node L2 norm (thread per node) ------------------------------
__global__ void norm_lit() {
    int n = blockIdx.x * blockDim.x + threadIdx.x;
    if (n >= NNODES) return;
    const float4* r = (const float4*)(g_outf + (size_t)n * D_EMBC);
    float s = 0.f;
    for (int i = 0; i < D_EMBC / 4; i++) {
        float4 v = r[i];
        s += v.x * v.x + v.y * v.y + v.z * v.z + v.w * v.w;
    }
    g_norm[n] = sqrtf(s);
}

// ---------------- affinity -> M0 nnz values (thread per forward edge) ------------
__global__ void aff_lit(const int* __restrict__ ei, const float* __restrict__ co,
                        const float* __restrict__ W1c, const float* __restrict__ b1c,
                        const float* __restrict__ W2c, const float* __restrict__ b2c) {
    int e = blockIdx.x * blockDim.x + threadIdx.x;
    if (e >= EE) return;
    int t = ei[e], dn = ei[TWO_E + e];
    const float4* oa = (const float4*)(g_outf + (size_t)t  * D_EMBC);
    const float4* ob = (const float4*)(g_outf + (size_t)dn * D_EMBC);
    float dot = 0.f;
    for (int i = 0; i < D_EMBC / 4; i++) {
        float4 a = oa[i], b = ob[i];
        dot += a.x * b.x + a.y * b.y + a.z * b.z + a.w * b.w;
    }
    float cosv = dot / fmaxf(g_norm[t] * g_norm[dn], 1e-6f);

    float4 A = *(const float4*)(co + t * 4);
    float4 B = *(const float4*)(co + dn * 4);
    float lt0 = fmaxf(A.x, B.x), lt1 = fmaxf(A.y, B.y);
    float rb0 = fminf(A.z, B.z), rb1 = fminf(A.w, B.w);
    float w = fmaxf(rb0 - lt0, 0.f), h = fmaxf(rb1 - lt1, 0.f);
    float inter = w * h;
    float areaA = (A.z - A.x) * (A.w - A.y);
    float areaB = (B.z - B.x) * (B.w - B.y);
    float iou = inter / (areaA + areaB - inter + 1e-9f);

    float aff = b2c[0];
    #pragma unroll
    for (int hh = 0; hh < 8; hh++)
        aff += fmaxf(cosv * W1c[hh] + iou * W1c[8 + hh] + b1c[hh], 0.f) * W2c[hh];
    g_mval[e] = expf(aff * LAMC);
    g_dstd[e] = dn - T_NUMC;
}

// ---------------- pack column view of M0 nnz (det-major) -------------------------
__global__ void csc_pack() {
    int idx = blockIdx.x * blockDim.x + threadIdx.x;  // EE threads
    int c = idx >> 6, k = idx & 63;
    int base = (T_NUMC + c) * 64 + k;                 // CSC of det node T+c: fwd edges only
    g_cval[idx] = g_mval[g_csc_eid[base]];
    g_csrc[idx] = g_csc_src[base];
}

// ---------------- factorized sinkhorn half-steps (warp per row, coalesced) -------
// row r: s = sum_k mval[r,k]*v[dstd[r,k]] + slack*v[1024];  u_r' = u_r/(u_r*s+eps)
__global__ void sink_row(float slack) {
    int tid = threadIdx.x, lane = tid & 31, wid = tid >> 5;
    if (blockIdx.x < 128) {
        int r = blockIdx.x * 8 + wid;
        const float* mv = g_mval + r * 64;
        const int*   dp = g_dstd + r * 64;
        float s = mv[lane] * g_v[dp[lane]] + mv[32 + lane] * g_v[dp[32 + lane]];
        s = warpsum(s);
        if (lane == 0) {
            s += slack * g_v[1024];
            float ur = g_u[r];
            g_u[r] = ur / (ur * s + EPSC);
        }
    } else {
        // slack row 1024: s = slack * sum_j v_j
        float s = 0.f;
        for (int i = tid; i < 1025; i += 256) s += g_v[i];
        __shared__ float red[8];
        float w = warpsum(s);
        if (lane == 0) red[wid] = w;
        __syncthreads();
        if (tid == 0) {
            float tot = 0.f;
            #pragma unroll
            for (int i = 0; i < 8; i++) tot += red[i];
            float ur = g_u[1024];
            g_u[1024] = ur / (ur * slack * tot + EPSC);
        }
    }
}

__global__ void sink_col(float slack) {
    int tid = threadIdx.x, lane = tid & 31, wid = tid >> 5;
    if (blockIdx.x < 128) {
        int c = blockIdx.x * 8 + wid;
        const float* cv = g_cval + c * 64;
        const int*   sp = g_csrc + c * 64;
        float s = cv[lane] * g_u[sp[lane]] + cv[32 + lane] * g_u[sp[32 + lane]];
        s = warpsum(s);
        if (lane == 0) {
            s += slack * g_u[1024];
            float vc = g_v[c];
            g_v[c] = vc / (vc * s + EPSC);
        }
    } else {
        float s = 0.f;
        for (int i = tid; i < 1025; i += 256) s += g_u[i];
        __shared__ float red[8];
        float w = warpsum(s);
        if (lane == 0) red[wid] = w;
        __syncthreads();
        if (tid == 0) {
            float tot = 0.f;
            #pragma unroll
            for (int i = 0; i < 8; i++) tot += red[i];
            float vc = g_v[1024];
            g_v[1024] = vc / (vc * slack * tot + EPSC);
        }
    }
}

// ---------------- final scatter: out[t,d] = u[t]*M0*v[d]; scalars ----------------
__global__ void out_scatter(float* __restrict__ out, int out_size) {
    int e = blockIdx.x * blockDim.x + threadIdx.x;
    if (e < EE) {
        int t = e >> 6;                 // forward edge e belongs to tracklet e/64
        int d = g_dstd[e];
        out[(size_t)t * DET_NUMC + d] = g_u[t] * g_mval[e] * g_v[d];
    }
    if (e == 0 && out_size >= 2097154) {
        out[2097152] = 1024.0f;  // det_num
        out[2097153] = 1024.0f;  // tracklet_num
    }
}

// =================================================================================
extern "C" void kernel_launch(void* const* d_in, const int* in_sizes, int n_in,
                              void* d_out, int out_size) {
    const float* x      = (const float*)d_in[0];
    const float* coords = (const float*)d_in[1];   // U[0,1) coords -> geo MLP
    const float* co     = (const float*)d_in[2];   // coords_original -> IoU
    const float* gt     = (const float*)d_in[3];
    const int*   ei     = (const int*)  d_in[4];
    const float* W_enc  = (const float*)d_in[5];
    const float* b_enc  = (const float*)d_in[6];
    const float* W1a    = (const float*)d_in[7];
    const float* b1a    = (const float*)d_in[8];
    const float* W2a    = (const float*)d_in[9];
    const float* b2a    = (const float*)d_in[10];
    const float* W1g    = (const float*)d_in[11];
    const float* b1g    = (const float*)d_in[12];
    const float* W2g    = (const float*)d_in[13];
    const float* b2g    = (const float*)d_in[14];
    const float* W1f    = (const float*)d_in[15];
    const float* b1f    = (const float*)d_in[16];
    const float* W2f    = (const float*)d_in[17];
    const float* b2f    = (const float*)d_in[18];
    const float* Wn     = (const float*)d_in[19];
    const float* Wm     = (const float*)d_in[20];
    const float* bo     = (const float*)d_in[21];
    const float* W1c    = (const float*)d_in[22];
    const float* b1c    = (const float*)d_in[23];
    const float* W2c    = (const float*)d_in[24];
    const float* b2c    = (const float*)d_in[25];

    void* p;
    cudaGetSymbolAddress(&p, g_node); float* node = (float*)p;
    cudaGetSymbolAddress(&p, g_msg);  float* msgp = (float*)p;
    cudaGetSymbolAddress(&p, g_outf); float* outp = (float*)p;

    init_kernel<<<8, 512>>>();
    csc_build<<<TWO_E / 256, 256>>>(ei);

    // node = relu(x @ W_enc + b_enc)
    sgemm<true,  false><<<dim3(4, 32), 256>>>(x, W_enc, nullptr, nullptr, b_enc,
                                              node, NNODES, D_EMBC, 512);
    // P = node @ W1a[:256] + b1a ;  Q = node @ W1a[256:]   (one fused launch)
    pq_gemm<<<dim3(2, 32), 256>>>(node, W1a, b1a);

    edge_pq<<<TWO_E / 256, 256>>>(ei, coords, W2a, b2a,
                                  W1g, b1g, W2g, b2g, W1f, b1f, W2f, b2f);
    msg_lit<<<(NNODES * D_EMBC) / 256, 256>>>();

    // out = relu(node @ Wn + msg @ Wm + bo)
    sgemm<true, true><<<dim3(4, 32), 256>>>(node, Wn, msgp, Wm, bo,
                                            outp, NNODES, D_EMBC, D_EMBC);

    norm_lit<<<NNODES / 256, 256>>>();
    aff_lit<<<EE / 256, 256>>>(ei, co, W1c, b1c, W2c, b2c);
    csc_pack<<<EE / 256, 256>>>();

    float slack = expf(-1.0f);  // exp(SLACK*LAM)
    for (int it = 0; it < 8; it++) {
        sink_row<<<129, 256>>>(slack);
        sink_col<<<129, 256>>>(slack);
    }

    cudaMemsetAsync(d_out, 0, (size_t)T_NUMC * DET_NUMC * sizeof(float), 0);
    out_scatter<<<EE / 256, 256>>>((float*)d_out, out_size);
    if (out_size >= 2097152)
        cudaMemcpyAsync((float*)d_out + 1048576, gt, 1048576 * sizeof(float),
                        cudaMemcpyDeviceToDevice, 0);
}